// round 16
// baseline (speedup 1.0000x reference)
#include <cuda_runtime.h>
#include <math.h>

#define Nn 50000
#define Ee 800000
#define Hh 64
#define Ll 2048
#define NBLK 196   /* ceil(Nn/256) */

/* ---------------- device scratch (no allocs allowed) ---------------- */
__device__ float g_xw[Nn * Hh];
__device__ float g_z[Nn * Hh];
__device__ float g_deg[Nn];
__device__ float g_dinv[Nn];
__device__ int   g_mask[Nn];
__device__ float g_pre0[(Ll + 1) * 256];   /* extra row so prefetch can read unconditionally */
__device__ float g_hfinal[Hh];
__device__ float g_logits[Nn];
__device__ float g_pL[NBLK];
__device__ float g_pY[NBLK];
__device__ int   g_pI[NBLK];
__device__ float g_pS[NBLK];
__device__ float g_lmax;
__device__ float g_sum;
__device__ int   g_next;

typedef unsigned long long ull;

/* packed f32x2 helpers (FFMA2 only reachable via PTX fma.rn.f32x2) */
#define FMA2(acc, w, h) asm("fma.rn.f32x2 %0, %1, %2, %0;" : "+l"(acc) : "l"(w), "l"(h))
__device__ __forceinline__ ull pk2(float a, float b) {
    ull r; asm("mov.b64 %0, {%1, %2};" : "=l"(r) : "f"(a), "f"(b)); return r;
}
__device__ __forceinline__ float sum2(ull v) {
    float a, b; asm("mov.b64 {%0, %1}, %2;" : "=f"(a), "=f"(b) : "l"(v)); return a + b;
}

/* fast activations */
__device__ __forceinline__ float fsig(float x) {
    return __fdividef(1.0f, 1.0f + __expf(-x));
}
__device__ __forceinline__ float ftan(float x) {
    float xc = fminf(fmaxf(x, -15.0f), 15.0f);
    float e = __expf(2.0f * xc);
    return __fdividef(e - 1.0f, e + 1.0f);
}

/* ---------------- cluster / mbarrier primitives ---------------- */
__device__ __forceinline__ unsigned smem_u32(const void* p) {
    return (unsigned)__cvta_generic_to_shared(p);
}
__device__ __forceinline__ unsigned mapa_rank(unsigned addr, unsigned r) {
    unsigned out;
    asm("mapa.shared::cluster.u32 %0, %1, %2;" : "=r"(out) : "r"(addr), "r"(r));
    return out;
}
__device__ __forceinline__ void mb_init(unsigned addr, unsigned cnt) {
    asm volatile("mbarrier.init.shared.b64 [%0], %1;" :: "r"(addr), "r"(cnt) : "memory");
}
__device__ __forceinline__ void mb_arrive_remote(unsigned cluster_addr) {
    asm volatile("mbarrier.arrive.release.cluster.shared::cluster.b64 _, [%0];"
                 :: "r"(cluster_addr) : "memory");
}
__device__ __forceinline__ void st_cluster_f32(unsigned cluster_addr, float v) {
    asm volatile("st.shared::cluster.f32 [%0], %1;" :: "r"(cluster_addr), "f"(v) : "memory");
}
__device__ __forceinline__ void wait_parity_cluster(unsigned addr, unsigned parity) {
    asm volatile(
        "{\n\t.reg .pred P;\n\t"
        "WL_%=:\n\t"
        "mbarrier.try_wait.parity.acquire.cluster.shared::cta.b64 P, [%0], %1, 0x989680;\n\t"
        "@P bra.uni WD_%=;\n\t"
        "bra.uni WL_%=;\n\t"
        "WD_%=:\n\t}"
        :: "r"(addr), "r"(parity) : "memory");
}
#define CLUSTER_SYNC() do { \
    asm volatile("barrier.cluster.arrive.aligned;" ::: "memory"); \
    asm volatile("barrier.cluster.wait.aligned;" ::: "memory"); \
} while (0)

/* Threefry-2x32, key (k0,k1). */
__device__ __forceinline__ void threefry2x32(unsigned k0, unsigned k1,
                                             unsigned& x0, unsigned& x1) {
    unsigned ks2 = k0 ^ k1 ^ 0x1BD11BDAu;
#define TF_R4(a,b,c,d) \
    x0 += x1; x1 = __funnelshift_l(x1, x1, (a)); x1 ^= x0; \
    x0 += x1; x1 = __funnelshift_l(x1, x1, (b)); x1 ^= x0; \
    x0 += x1; x1 = __funnelshift_l(x1, x1, (c)); x1 ^= x0; \
    x0 += x1; x1 = __funnelshift_l(x1, x1, (d)); x1 ^= x0;
    x0 += k0;  x1 += k1;
    TF_R4(13,15,26,6);  x0 += k1;  x1 += ks2 + 1u;
    TF_R4(17,29,16,24); x0 += ks2; x1 += k0  + 2u;
    TF_R4(13,15,26,6);  x0 += k0;  x1 += k1  + 3u;
    TF_R4(17,29,16,24); x0 += k1;  x1 += ks2 + 4u;
    TF_R4(13,15,26,6);  x0 += ks2; x1 += k0  + 5u;
#undef TF_R4
}

/* ---------------- GCN kernels ---------------- */
__global__ void k_zero() {
    int i = blockIdx.x * blockDim.x + threadIdx.x;
    int stride = gridDim.x * blockDim.x;
    for (int j = i; j < Nn * Hh; j += stride) g_z[j] = 0.f;
    for (int j = i; j < Nn; j += stride) { g_deg[j] = 0.f; g_mask[j] = 0; }
}

__global__ void k_setup(const int* ei, const float* ew, const int* visited) {
    int i = blockIdx.x * blockDim.x + threadIdx.x;
    if (i < Ee) {
        atomicAdd(&g_deg[ei[Ee + i]], ew[i]);
    } else if (i < Ee + Nn) {
        atomicAdd(&g_deg[i - Ee], 1.0f);
    } else if (i < Ee + Nn + Ll) {
        g_mask[visited[i - Ee - Nn]] = 1;
    }
}

/* 64 rows per block; W1 staged once in shared */
__global__ void k_xw(const float* __restrict__ x, const float* __restrict__ W1) {
    __shared__ __align__(16) float Ws[64 * 64];
    __shared__ __align__(16) float xs[4 * 64];
    int tid = threadIdx.x;
    for (int i = tid; i < 4096; i += 256) Ws[i] = W1[i];
    int row0 = blockIdx.x * 64;
    int col = tid & 63, rg = tid >> 6;
    for (int it = 0; it < 16; it++) {
        int row = row0 + it * 4 + rg;
        __syncthreads();
        xs[tid] = (row < Nn) ? x[row * 64 + col] : 0.f;
        __syncthreads();
        if (row < Nn) {
            float acc = 0.f;
            const float4* xr = (const float4*)(xs + rg * 64);
#pragma unroll
            for (int j = 0; j < 16; j++) {
                float4 xv = xr[j];
                acc += xv.x * Ws[(4 * j + 0) * 64 + col] + xv.y * Ws[(4 * j + 1) * 64 + col]
                     + xv.z * Ws[(4 * j + 2) * 64 + col] + xv.w * Ws[(4 * j + 3) * 64 + col];
            }
            g_xw[row * 64 + col] = acc;
        }
    }
}

__global__ void k_dinv() {
    int n = blockIdx.x * 256 + threadIdx.x;
    if (n < Nn) { float d = g_deg[n]; g_dinv[n] = (d > 0.f) ? 1.0f / sqrtf(d) : 0.f; }
}

__global__ void k_scatter(const int* __restrict__ ei, const float* __restrict__ ew) {
    int idx = blockIdx.x * 256 + threadIdx.x;
    if (idx >= Ee * 4) return;
    int e = idx >> 2, part = idx & 3;
    int s = ei[e], d = ei[Ee + e];
    float norm = g_dinv[s] * ew[e] * g_dinv[d];
    const float4* xp = (const float4*)(g_xw + s * 64) + part * 4;
    float* zp = g_z + d * 64 + part * 16;
#pragma unroll
    for (int q = 0; q < 4; q++) {
        float4 v = xp[q];
        asm volatile("red.global.add.v4.f32 [%0], {%1, %2, %3, %4};"
                     :: "l"(zp + 4 * q),
                        "f"(norm * v.x), "f"(norm * v.y),
                        "f"(norm * v.z), "f"(norm * v.w) : "memory");
    }
}

__global__ void k_fin(const float* __restrict__ b1) {
    int idx = blockIdx.x * 256 + threadIdx.x;
    if (idx >= Nn * 16) return;
    int n = idx >> 4, q = idx & 15;
    float di = g_dinv[n];
    float c = di * di;
    float4 v = ((const float4*)g_xw)[idx];
    float4 z = ((float4*)g_z)[idx];
    float4 b = ((const float4*)b1)[q];
    z.x += c * v.x + b.x;
    z.y += c * v.y + b.y;
    z.z += c * v.z + b.z;
    z.w += c * v.w + b.w;
    ((float4*)g_z)[idx] = z;
}

__global__ void k_pre0(const float* __restrict__ Wih0, const float* __restrict__ bih0,
                       const float* __restrict__ bhh0, const int* __restrict__ visited) {
    __shared__ __align__(16) float seq[64];
    int t = blockIdx.x, g = threadIdx.x;
    if (g < 64) seq[g] = g_z[visited[t] * 64 + g];
    __syncthreads();
    float acc = bih0[g] + bhh0[g];
    const float4* w = (const float4*)(Wih0 + g * 64);
    const float4* h4 = (const float4*)seq;
#pragma unroll
    for (int j = 0; j < 16; j++) {
        float4 wv = w[j]; float4 hv = h4[j];
        acc += wv.x * hv.x + wv.y * hv.y + wv.z * hv.z + wv.w * hv.w;
    }
    g_pre0[t * 256 + g] = acc;
}

/* ---------------- 2-CTA cluster-pipelined LSTM ----------------
   rank 0: layer 0 (Whh0).  rank 1: layer 1 (Wih1, Whh1).
   h0[t] handed rank0 -> rank1 via DSMEM, 2-slot ring.
   full[slot] on rank1 smem (count=64, arrived remotely by rank0 threads g<64)
   empty[slot] on rank0 smem (count=1, arrived remotely by rank1 thread 0)     */
__global__ __launch_bounds__(256, 1) __cluster_dims__(2, 1, 1)
void k_lstm2(const float* __restrict__ Whh0, const float* __restrict__ Wih1,
             const float* __restrict__ Whh1, const float* __restrict__ bih1,
             const float* __restrict__ bhh1) {
    __shared__ __align__(16) float hs[64];          /* h0 (rank0) / h1 (rank1) */
    __shared__ __align__(16) float gates[256];
    __shared__ __align__(16) float h0buf[2][64];    /* used on rank1 */
    __shared__ __align__(8) ull mb_full[2];         /* used on rank1 */
    __shared__ __align__(8) ull mb_empty[2];        /* used on rank0 */

    int g = threadIdx.x;
    unsigned rank; asm("mov.u32 %0, %%cluster_ctarank;" : "=r"(rank));
    unsigned full_a  = smem_u32(mb_full);
    unsigned empty_a = smem_u32(mb_empty);

    if (g == 0) {
        mb_init(full_a + 0, 64);  mb_init(full_a + 8, 64);
        mb_init(empty_a + 0, 1);  mb_init(empty_a + 8, 1);
    }
    if (g < 64) hs[g] = 0.f;
    __syncthreads();
    CLUSTER_SYNC();

    const ull* H = (const ull*)hs;

    if (rank == 0) {
        /* layer 0: 64 regs of Whh0 row g, packed */
        ull w0[32];
        {
            const ulonglong2* p0 = (const ulonglong2*)(Whh0 + g * 64);
#pragma unroll
            for (int j = 0; j < 16; j++) { ulonglong2 a = p0[j]; w0[2*j] = a.x; w0[2*j+1] = a.y; }
        }
        float c0 = 0.f;
        float pnext = g_pre0[g];
        unsigned h0buf_a = smem_u32(h0buf);
        for (int t = 0; t < Ll; t++) {
            float p = pnext;
            pnext = g_pre0[(t + 1) * 256 + g];
            ull acc = pk2(p, 0.0f);
#pragma unroll
            for (int k = 0; k < 32; k++) FMA2(acc, w0[k], H[k]);
            float s = sum2(acc);
            gates[g] = ((g >> 6) == 2) ? ftan(s) : fsig(s);  /* gate-local activation */
            __syncthreads();
            int slot = t & 1;
            if (g < 64) {
                float i = gates[g], f = gates[64 + g], gg = gates[128 + g], o = gates[192 + g];
                c0 = f * c0 + i * gg;
                float h = o * ftan(c0);
                hs[g] = h;
                /* backpressure: slot must be consumed (2 steps ago) */
                wait_parity_cluster(empty_a + slot * 8, 1u ^ ((unsigned)(t >> 1) & 1u));
                unsigned raddr = mapa_rank(h0buf_a + (slot * 64 + g) * 4, 1);
                st_cluster_f32(raddr, h);
                mb_arrive_remote(mapa_rank(full_a + slot * 8, 1));  /* release: orders the store */
            }
            __syncthreads();
        }
    } else {
        /* layer 1: Wih1 + Whh1 rows, packed */
        ull wi[32], wh[32];
        {
            const ulonglong2* p1 = (const ulonglong2*)(Wih1 + g * 64);
            const ulonglong2* p2 = (const ulonglong2*)(Whh1 + g * 64);
#pragma unroll
            for (int j = 0; j < 16; j++) {
                ulonglong2 b = p1[j]; wi[2*j] = b.x; wi[2*j+1] = b.y;
                ulonglong2 c = p2[j]; wh[2*j] = c.x; wh[2*j+1] = c.y;
            }
        }
        float bias1 = bih1[g] + bhh1[g];
        float c1 = 0.f;
        for (int t = 0; t < Ll; t++) {
            int slot = t & 1;
            ull acc = pk2(bias1, 0.0f);
#pragma unroll
            for (int k = 0; k < 32; k++) FMA2(acc, wh[k], H[k]);   /* overlaps with wait */
            wait_parity_cluster(full_a + slot * 8, (unsigned)(t >> 1) & 1u);
            const ull* HB = (const ull*)h0buf[slot];
#pragma unroll
            for (int k = 0; k < 32; k++) FMA2(acc, wi[k], HB[k]);
            float s = sum2(acc);
            gates[g] = ((g >> 6) == 2) ? ftan(s) : fsig(s);
            __syncthreads();                                      /* all h0buf reads done */
            if (g == 0) mb_arrive_remote(mapa_rank(empty_a + slot * 8, 0));
            if (g < 64) {
                float i = gates[g], f = gates[64 + g], gg = gates[128 + g], o = gates[192 + g];
                c1 = f * c1 + i * gg;
                hs[g] = o * ftan(c1);
            }
            __syncthreads();
        }
        if (g < 64) g_hfinal[g] = hs[g];
    }
    CLUSTER_SYNC();   /* no CTA exits while peer arrives are in flight */
}

/* ---------------- scoring / sampling ---------------- */
__global__ void k_logits() {
    __shared__ __align__(16) float hf[64];
    __shared__ float sL[256], sY[256];
    __shared__ int sI[256];
    int t = threadIdx.x;
    int n = blockIdx.x * 256 + t;
    if (t < 64) hf[t] = g_hfinal[t];
    __syncthreads();
    float L = -INFINITY, Y = -INFINITY;
    int I = (n < Nn) ? n : 0x7fffffff;
    if (n < Nn) {
        float acc = 0.f;
        const float4* z4 = (const float4*)(g_z + n * 64);
        const float4* h4 = (const float4*)hf;
#pragma unroll
        for (int j = 0; j < 16; j++) {
            float4 a = z4[j]; float4 b = h4[j];
            acc += a.x*b.x + a.y*b.y + a.z*b.z + a.w*b.w;
        }
        L = g_mask[n] ? -INFINITY : acc;
        g_logits[n] = L;
        unsigned x0 = 0u, x1 = (unsigned)n;
        threefry2x32(0u, 1u, x0, x1);
        unsigned bits = x0 ^ x1;
        float f = __uint_as_float((bits >> 9) | 0x3f800000u) - 1.0f;
        const float tiny = 1.1754944e-38f;
        float u = fmaxf(tiny, f * (1.0f - tiny) + tiny);
        float gum = -logf(-logf(u));
        Y = L + gum;
    }
    sL[t] = L; sY[t] = Y; sI[t] = I;
    __syncthreads();
    for (int s = 128; s > 0; s >>= 1) {
        if (t < s) {
            sL[t] = fmaxf(sL[t], sL[t + s]);
            float y2 = sY[t + s]; int i2 = sI[t + s];
            if (y2 > sY[t] || (y2 == sY[t] && i2 < sI[t])) { sY[t] = y2; sI[t] = i2; }
        }
        __syncthreads();
    }
    if (t == 0) { g_pL[blockIdx.x] = sL[0]; g_pY[blockIdx.x] = sY[0]; g_pI[blockIdx.x] = sI[0]; }
}

__global__ void k_red1() {
    __shared__ float sL[256], sY[256];
    __shared__ int sI[256];
    int t = threadIdx.x;
    sL[t] = (t < NBLK) ? g_pL[t] : -INFINITY;
    sY[t] = (t < NBLK) ? g_pY[t] : -INFINITY;
    sI[t] = (t < NBLK) ? g_pI[t] : 0x7fffffff;
    __syncthreads();
    for (int s = 128; s > 0; s >>= 1) {
        if (t < s) {
            sL[t] = fmaxf(sL[t], sL[t + s]);
            float y2 = sY[t + s]; int i2 = sI[t + s];
            if (y2 > sY[t] || (y2 == sY[t] && i2 < sI[t])) { sY[t] = y2; sI[t] = i2; }
        }
        __syncthreads();
    }
    if (t == 0) { g_lmax = sL[0]; g_next = sI[0]; }
}

__global__ void k_esum() {
    __shared__ float sm[256];
    int t = threadIdx.x;
    int n = blockIdx.x * 256 + t;
    float e = 0.f;
    if (n < Nn) e = expf(g_logits[n] - g_lmax);
    sm[t] = e;
    __syncthreads();
    for (int s2 = 128; s2 > 0; s2 >>= 1) {
        if (t < s2) sm[t] += sm[t + s2];
        __syncthreads();
    }
    if (t == 0) g_pS[blockIdx.x] = sm[0];
}

__global__ void k_red2(float* out, int off) {
    __shared__ float sm[256];
    int t = threadIdx.x;
    sm[t] = (t < NBLK) ? g_pS[t] : 0.f;
    __syncthreads();
    for (int s2 = 128; s2 > 0; s2 >>= 1) {
        if (t < s2) sm[t] += sm[t + s2];
        __syncthreads();
    }
    if (t == 0) {
        g_sum = sm[0];
        if (off > 0) out[0] = (float)g_next;
    }
}

__global__ void k_probs(float* out, int off) {
    int n = blockIdx.x * 256 + threadIdx.x;
    if (n < Nn) out[off + n] = expf(g_logits[n] - g_lmax) / g_sum;
}

/* ---------------- launcher ---------------- */
extern "C" void kernel_launch(void* const* d_in, const int* in_sizes, int n_in,
                              void* d_out, int out_size) {
    const float* x       = (const float*)d_in[0];
    const int*   ei      = (const int*)d_in[1];
    const float* ew      = (const float*)d_in[2];
    const int*   visited = (const int*)d_in[3];
    const float* W1      = (const float*)d_in[4];
    const float* b1      = (const float*)d_in[5];
    const float* Wih0    = (const float*)d_in[6];
    const float* Whh0    = (const float*)d_in[7];
    const float* bih0    = (const float*)d_in[8];
    const float* bhh0    = (const float*)d_in[9];
    const float* Wih1    = (const float*)d_in[10];
    const float* Whh1    = (const float*)d_in[11];
    const float* bih1    = (const float*)d_in[12];
    const float* bhh1    = (const float*)d_in[13];
    float* out = (float*)d_out;
    int off = (out_size > Nn) ? (out_size - Nn) : 0;

    k_zero<<<2048, 256>>>();
    k_setup<<<(Ee + Nn + Ll + 255) / 256, 256>>>(ei, ew, visited);
    k_xw<<<(Nn + 63) / 64, 256>>>(x, W1);
    k_dinv<<<NBLK, 256>>>();
    k_scatter<<<(Ee * 4 + 255) / 256, 256>>>(ei, ew);
    k_fin<<<(Nn * 16 + 255) / 256, 256>>>(b1);
    k_pre0<<<Ll, 256>>>(Wih0, bih0, bhh0, visited);
    k_lstm2<<<2, 256>>>(Whh0, Wih1, Whh1, bih1, bhh1);
    k_logits<<<NBLK, 256>>>();
    k_red1<<<1, 256>>>();
    k_esum<<<NBLK, 256>>>();
    k_red2<<<1, 256>>>(out, off);
    k_probs<<<NBLK, 256>>>(out, off);
}